// round 8
// baseline (speedup 1.0000x reference)
#include <cuda_runtime.h>
#include <cuda_fp16.h>
#include <cstdint>

#define Tt 4
#define Nn 50000
#define Ee 800000
#define Dd 256
#define D4 64
#define NT (Tt * Nn)        // 200000
#define ET (Tt * Ee)        // 3200000
#define SCAN_BLK 49         // ceil(200000/4096)

// ---------------- scratch ----------------
__device__ __half g_h0[(size_t)Nn * Dd];
__device__ __half g_h1[(size_t)Nn * Dd];
__device__ __half g_h2[(size_t)Nn * Dd];
__device__ __half g_h3[(size_t)Nn * Dd];
__device__ __half g_x[(size_t)NT * Dd];      // X (fp16)
__device__ __half g_w[3][Dd * Dd];           // W^T (fp16) [N,K]
__device__ float g_dinv[NT];
__device__ int   g_cnt[NT];
__device__ int   g_cur[NT];
__device__ int   g_ptr[NT + 1];
__device__ int   g_bsum[64];
__device__ int   g_boff[64];
__device__ int   g_erow[ET];
__device__ float g_enorm[ET];

// ---------------- helpers ----------------
__device__ __forceinline__ void h8f(uint4 v, float* f) {
    float2 p;
    p = __half22float2(*reinterpret_cast<__half2*>(&v.x)); f[0] = p.x; f[1] = p.y;
    p = __half22float2(*reinterpret_cast<__half2*>(&v.y)); f[2] = p.x; f[3] = p.y;
    p = __half22float2(*reinterpret_cast<__half2*>(&v.z)); f[4] = p.x; f[5] = p.y;
    p = __half22float2(*reinterpret_cast<__half2*>(&v.w)); f[6] = p.x; f[7] = p.y;
}
__device__ __forceinline__ uint32_t f2h2(float a, float b) {
    __half2 t = __floats2half2_rn(a, b);
    return *reinterpret_cast<uint32_t*>(&t);
}

// ---------------- batched prep ----------------
__global__ void k_init(float* __restrict__ deg, int* __restrict__ cnt) {
    int i = blockIdx.x * blockDim.x + threadIdx.x;
    if (i < NT) { deg[i] = 1.0f; cnt[i] = 0; }
}

__global__ void k_edge_prep(const int* __restrict__ ei_all, const float* __restrict__ w_all,
                            float* __restrict__ deg, int* __restrict__ cnt) {
    int ge = blockIdx.x * blockDim.x + threadIdx.x;
    if (ge < ET) {
        int t = ge / Ee, e = ge - t * Ee;
        int c = ei_all[(size_t)t * 2 * Ee + Ee + e];
        int gc = t * Nn + c;
        atomicAdd(&deg[gc], w_all[ge]);
        atomicAdd(&cnt[gc], 1);
    }
}

__global__ void k_finalize_dinv(float* __restrict__ deg) {
    int i = blockIdx.x * blockDim.x + threadIdx.x;
    if (i < NT) {
        float d = deg[i];
        deg[i] = (d > 0.0f) ? rsqrtf(d) : 0.0f;
    }
}

__global__ void __launch_bounds__(1024)
k_scan1(const int* __restrict__ cnt, int* __restrict__ ptr, int* __restrict__ cur,
        int* __restrict__ bsum) {
    __shared__ int wt[32];
    int tid = threadIdx.x, lane = tid & 31, wid = tid >> 5;
    int i0 = blockIdx.x * 4096 + tid * 4;
    int4 v = make_int4(0, 0, 0, 0);
    if (i0 + 3 < NT) v = *(const int4*)(cnt + i0);
    else {
        if (i0 < NT)     v.x = cnt[i0];
        if (i0 + 1 < NT) v.y = cnt[i0 + 1];
        if (i0 + 2 < NT) v.z = cnt[i0 + 2];
    }
    int tsum = v.x + v.y + v.z + v.w;
    int s = tsum;
#pragma unroll
    for (int off = 1; off < 32; off <<= 1) {
        int t = __shfl_up_sync(0xffffffffu, s, off);
        if (lane >= off) s += t;
    }
    if (lane == 31) wt[wid] = s;
    __syncthreads();
    if (wid == 0) {
        int ws = wt[lane];
#pragma unroll
        for (int off = 1; off < 32; off <<= 1) {
            int t = __shfl_up_sync(0xffffffffu, ws, off);
            if (lane >= off) ws += t;
        }
        wt[lane] = ws;
    }
    __syncthreads();
    int excl = s - tsum + (wid > 0 ? wt[wid - 1] : 0);
    int p = excl;
    if (i0 < NT)     { cur[i0] = p;     ptr[i0 + 1] = p + v.x; } p += v.x;
    if (i0 + 1 < NT) { cur[i0 + 1] = p; ptr[i0 + 2] = p + v.y; } p += v.y;
    if (i0 + 2 < NT) { cur[i0 + 2] = p; ptr[i0 + 3] = p + v.z; } p += v.z;
    if (i0 + 3 < NT) { cur[i0 + 3] = p; ptr[i0 + 4] = p + v.w; }
    if (tid == 1023) bsum[blockIdx.x] = excl + tsum;
}

__global__ void k_scan2(const int* __restrict__ bsum, int* __restrict__ boff,
                        int* __restrict__ ptr) {
    if (threadIdx.x == 0) {
        ptr[0] = 0;
        int run = 0;
        for (int b = 0; b < SCAN_BLK; b++) { boff[b] = run; run += bsum[b]; }
    }
}

__global__ void __launch_bounds__(1024)
k_scan3(const int* __restrict__ boff, int* __restrict__ ptr, int* __restrict__ cur) {
    int off = boff[blockIdx.x];
    int i0 = blockIdx.x * 4096 + threadIdx.x * 4;
#pragma unroll
    for (int k = 0; k < 4; k++) {
        int i = i0 + k;
        if (i < NT) { cur[i] += off; ptr[i + 1] += off; }
    }
}

__global__ void k_permute(const int* __restrict__ ei_all, const float* __restrict__ w_all,
                          const float* __restrict__ dinv, int* __restrict__ cur,
                          int* __restrict__ erow, float* __restrict__ enorm) {
    int ge = blockIdx.x * blockDim.x + threadIdx.x;
    if (ge < ET) {
        int t = ge / Ee, e = ge - t * Ee;
        const int* base = ei_all + (size_t)t * 2 * Ee;
        int r = base[e], c = base[Ee + e];
        int gr = t * Nn + r, gc = t * Nn + c;
        float nm = dinv[gr] * w_all[ge] * dinv[gc];
        int pos = atomicAdd(&cur[gc], 1);
        erow[pos] = r;
        enorm[pos] = nm;
    }
}

// W^T fp16: w[n*256+k] = fp16(W[k*256+n])
__global__ void k_wprep(const float* __restrict__ W, __half* __restrict__ wt) {
    int idx = blockIdx.x * blockDim.x + threadIdx.x;
    if (idx < Dd * Dd) {
        int n = idx >> 8, k = idx & 255;
        wt[idx] = __float2half_rn(W[k * Dd + n]);
    }
}

// embedding gather -> fp16 x
__global__ void k_gather(const int* __restrict__ ids, const float4* __restrict__ emb,
                         uint2* __restrict__ x) {
    int idx = blockIdx.x * blockDim.x + threadIdx.x;
    if (idx < NT * 64) {
        int i = idx >> 6, q = idx & 63;
        float4 v = emb[(size_t)ids[i] * 64 + q];
        x[idx] = make_uint2(f2h2(v.x, v.y), f2h2(v.z, v.w));
    }
}

// ---------------- mma.sync fp16 GEMM ----------------
__device__ __forceinline__ uint32_t swz(int row, int c) {
    return (uint32_t)(row * 64 + ((c ^ ((row >> 1) & 3)) << 4));
}

#define GEMM_SMEM 32768

__global__ void __launch_bounds__(256)
k_gemm_mma(const __half* __restrict__ x, const __half* __restrict__ wt,
           __half* __restrict__ H) {
    extern __shared__ __align__(128) char sm[];

    const int tid = threadIdx.x;
    const int wid = tid >> 5, lane = tid & 31;
    const int m0 = blockIdx.x * 128, n0 = blockIdx.y * 128;
    const int mw = wid >> 2, nw = wid & 3;

    float acc[4][4][4] = {};

    auto issue = [&](int kc, int stage) {
        char* sbase = sm + stage * 16384;
#pragma unroll
        for (int i = 0; i < 4; i++) {
            int u = tid + i * 256;
            int tile = u >> 9, idx = u & 511;
            int row = idx >> 2, c = idx & 3;
            uint32_t dst = (uint32_t)__cvta_generic_to_shared(
                sbase + tile * 8192 + swz(row, c));
            if (tile == 0) {
                int gm = m0 + row;
                int ok = (gm < Nn);
                const void* src = x + (size_t)(ok ? gm : 0) * Dd + kc * 32 + c * 8;
                int sz = ok ? 16 : 0;
                asm volatile("cp.async.ca.shared.global [%0], [%1], 16, %2;"
                             :: "r"(dst), "l"(src), "r"(sz));
            } else {
                const void* src = wt + (size_t)(n0 + row) * Dd + kc * 32 + c * 8;
                asm volatile("cp.async.ca.shared.global [%0], [%1], 16;"
                             :: "r"(dst), "l"(src));
            }
        }
        asm volatile("cp.async.commit_group;");
    };

    issue(0, 0);
    for (int it = 0; it < 8; it++) {
        int buf = it & 1;
        if (it + 1 < 8) {
            issue(it + 1, buf ^ 1);
            asm volatile("cp.async.wait_group 1;");
        } else {
            asm volatile("cp.async.wait_group 0;");
        }
        __syncthreads();
        char* pA = sm + buf * 16384;
        char* pB = pA + 8192;

#pragma unroll
        for (int ks = 0; ks < 2; ks++) {
            int ac = ks * 2 + ((lane >> 4) & 1);
            int brow = (lane & 7) + ((lane & 16) ? 8 : 0);
            int bc = ks * 2 + ((lane & 8) ? 1 : 0);
            uint32_t af[4][4];
#pragma unroll
            for (int mt = 0; mt < 4; mt++) {
                int row = mw * 64 + mt * 16 + (lane & 15);
                uint32_t a = (uint32_t)__cvta_generic_to_shared(pA + swz(row, ac));
                asm volatile("ldmatrix.sync.aligned.m8n8.x4.shared.b16 {%0,%1,%2,%3}, [%4];"
                             : "=r"(af[mt][0]), "=r"(af[mt][1]),
                               "=r"(af[mt][2]), "=r"(af[mt][3]) : "r"(a));
            }
            uint32_t bf[4][2];
#pragma unroll
            for (int ntp = 0; ntp < 2; ntp++) {
                int row = nw * 32 + ntp * 16 + brow;
                uint32_t b = (uint32_t)__cvta_generic_to_shared(pB + swz(row, bc));
                uint32_t r0, r1, r2, r3;
                asm volatile("ldmatrix.sync.aligned.m8n8.x4.shared.b16 {%0,%1,%2,%3}, [%4];"
                             : "=r"(r0), "=r"(r1), "=r"(r2), "=r"(r3) : "r"(b));
                bf[ntp * 2][0] = r0; bf[ntp * 2][1] = r1;
                bf[ntp * 2 + 1][0] = r2; bf[ntp * 2 + 1][1] = r3;
            }
#pragma unroll
            for (int mt = 0; mt < 4; mt++)
#pragma unroll
                for (int nt = 0; nt < 4; nt++) {
                    asm volatile(
                        "mma.sync.aligned.m16n8k16.row.col.f32.f16.f16.f32 "
                        "{%0,%1,%2,%3}, {%4,%5,%6,%7}, {%8,%9}, {%0,%1,%2,%3};"
                        : "+f"(acc[mt][nt][0]), "+f"(acc[mt][nt][1]),
                          "+f"(acc[mt][nt][2]), "+f"(acc[mt][nt][3])
                        : "r"(af[mt][0]), "r"(af[mt][1]), "r"(af[mt][2]), "r"(af[mt][3]),
                          "r"(bf[nt][0]), "r"(bf[nt][1]));
                }
        }
        __syncthreads();
    }

#pragma unroll
    for (int mt = 0; mt < 4; mt++) {
        int mm = m0 + mw * 64 + mt * 16 + (lane >> 2);
#pragma unroll
        for (int nt = 0; nt < 4; nt++) {
            int cc = n0 + nw * 32 + nt * 8 + 2 * (lane & 3);
            if (mm < Nn)
                *(uint32_t*)(H + (size_t)mm * Dd + cc) = f2h2(acc[mt][nt][0], acc[mt][nt][1]);
            if (mm + 8 < Nn)
                *(uint32_t*)(H + (size_t)(mm + 8) * Dd + cc) = f2h2(acc[mt][nt][2], acc[mt][nt][3]);
        }
    }
}

// ---------------- aggregate ----------------
__global__ void __launch_bounds__(256)
k_aggregate(const int* __restrict__ ptr, const int* __restrict__ erow,
            const float* __restrict__ enorm, const uint4* __restrict__ H,
            const float* __restrict__ dinv, const float4* __restrict__ bias,
            float4* __restrict__ outF, uint4* __restrict__ ox) {
    int warp = (blockIdx.x * blockDim.x + threadIdx.x) >> 5;
    int lane = threadIdx.x & 31;
    if (warp >= Nn) return;
    int node = warp;

    float s = dinv[node];
    s = s * s;
    float f[8], acc[8];
    h8f(H[(size_t)node * 32 + lane], f);
    float4 b0 = bias[lane * 2], b1 = bias[lane * 2 + 1];
    acc[0] = fmaf(s, f[0], b0.x); acc[1] = fmaf(s, f[1], b0.y);
    acc[2] = fmaf(s, f[2], b0.z); acc[3] = fmaf(s, f[3], b0.w);
    acc[4] = fmaf(s, f[4], b1.x); acc[5] = fmaf(s, f[5], b1.y);
    acc[6] = fmaf(s, f[6], b1.z); acc[7] = fmaf(s, f[7], b1.w);

    int jb = ptr[node], je = ptr[node + 1];
    int j = jb;
    for (; j + 1 < je; j += 2) {
        int ra = erow[j], rb = erow[j + 1];
        float na = enorm[j], nb = enorm[j + 1];
        uint4 va = H[(size_t)ra * 32 + lane];
        uint4 vb = H[(size_t)rb * 32 + lane];
        float fa[8], fb[8];
        h8f(va, fa); h8f(vb, fb);
#pragma unroll
        for (int i = 0; i < 8; i++) acc[i] = fmaf(na, fa[i], acc[i]);
#pragma unroll
        for (int i = 0; i < 8; i++) acc[i] = fmaf(nb, fb[i], acc[i]);
    }
    if (j < je) {
        int r = erow[j];
        float nm = enorm[j];
        float fr[8];
        h8f(H[(size_t)r * 32 + lane], fr);
#pragma unroll
        for (int i = 0; i < 8; i++) acc[i] = fmaf(nm, fr[i], acc[i]);
    }

    if (outF) {
        float4* op = outF + (size_t)node * D4 + lane * 2;
        op[0] = make_float4(acc[0], acc[1], acc[2], acc[3]);
        op[1] = make_float4(acc[4], acc[5], acc[6], acc[7]);
    }
    if (ox) {
        ox[(size_t)node * 32 + lane] = make_uint4(f2h2(acc[0], acc[1]), f2h2(acc[2], acc[3]),
                                                  f2h2(acc[4], acc[5]), f2h2(acc[6], acc[7]));
    }
}

// ---------------- launch ----------------
extern "C" void kernel_launch(void* const* d_in, const int* in_sizes, int n_in,
                              void* d_out, int out_size) {
    const int*   ids_all = (const int*)d_in[0];
    const int*   ei_all  = (const int*)d_in[1];
    const float* w_all   = (const float*)d_in[2];
    const float* emb     = (const float*)d_in[3];
    const float* Ws[3] = {(const float*)d_in[4], (const float*)d_in[6], (const float*)d_in[8]};
    const float* bs[3] = {(const float*)d_in[5], (const float*)d_in[7], (const float*)d_in[9]};
    float* out = (float*)d_out;

    void *ph0, *ph1, *ph2, *ph3, *px, *pw, *pd, *pc, *pu, *pp, *pe, *pm, *pbs, *pbo;
    cudaGetSymbolAddress(&ph0, g_h0);
    cudaGetSymbolAddress(&ph1, g_h1);
    cudaGetSymbolAddress(&ph2, g_h2);
    cudaGetSymbolAddress(&ph3, g_h3);
    cudaGetSymbolAddress(&px,  g_x);
    cudaGetSymbolAddress(&pw,  g_w);
    cudaGetSymbolAddress(&pd,  g_dinv);
    cudaGetSymbolAddress(&pc,  g_cnt);
    cudaGetSymbolAddress(&pu,  g_cur);
    cudaGetSymbolAddress(&pp,  g_ptr);
    cudaGetSymbolAddress(&pe,  g_erow);
    cudaGetSymbolAddress(&pm,  g_enorm);
    cudaGetSymbolAddress(&pbs, g_bsum);
    cudaGetSymbolAddress(&pbo, g_boff);
    __half* H[4] = {(__half*)ph0, (__half*)ph1, (__half*)ph2, (__half*)ph3};
    __half* x  = (__half*)px;
    __half* wt = (__half*)pw;
    float* dinv = (float*)pd;
    int* cnt = (int*)pc;
    int* cur = (int*)pu;
    int* ptr = (int*)pp;
    int* erow = (int*)pe;
    float* enrm = (float*)pm;
    int* bsum = (int*)pbs;
    int* boff = (int*)pbo;

    const int TPB = 256;
    static cudaStream_t st[4] = {nullptr, nullptr, nullptr, nullptr};
    static cudaEvent_t evStart = nullptr, evPrepG = nullptr, evPrepE = nullptr;
    static cudaEvent_t evFork = nullptr, evJoin[4] = {nullptr, nullptr, nullptr, nullptr};
    if (!st[1]) {
        st[0] = (cudaStream_t)0;
        for (int i = 1; i < 4; i++) cudaStreamCreateWithFlags(&st[i], cudaStreamNonBlocking);
        cudaEventCreateWithFlags(&evStart, cudaEventDisableTiming);
        cudaEventCreateWithFlags(&evPrepG, cudaEventDisableTiming);
        cudaEventCreateWithFlags(&evPrepE, cudaEventDisableTiming);
        cudaEventCreateWithFlags(&evFork, cudaEventDisableTiming);
        for (int i = 1; i < 4; i++) cudaEventCreateWithFlags(&evJoin[i], cudaEventDisableTiming);
        cudaFuncSetAttribute(k_gemm_mma, cudaFuncAttributeMaxDynamicSharedMemorySize,
                             GEMM_SMEM);
    }

    // ---- prep: two parallel branches ----
    cudaEventRecord(evStart, st[0]);
    cudaStreamWaitEvent(st[1], evStart, 0);

    // branch A (st[1]): weights + gather
    for (int l = 0; l < 3; l++)
        k_wprep<<<(Dd * Dd + TPB - 1) / TPB, TPB, 0, st[1]>>>(Ws[l],
                                                              wt + (size_t)l * Dd * Dd);
    k_gather<<<(NT * 64 + TPB - 1) / TPB, TPB, 0, st[1]>>>(ids_all, (const float4*)emb,
                                                           (uint2*)x);
    cudaEventRecord(evPrepG, st[1]);

    // branch B (st[0]): edge chain
    k_init<<<(NT + TPB - 1) / TPB, TPB, 0, st[0]>>>(dinv, cnt);
    k_edge_prep<<<(ET + TPB - 1) / TPB, TPB, 0, st[0]>>>(ei_all, w_all, dinv, cnt);
    k_finalize_dinv<<<(NT + TPB - 1) / TPB, TPB, 0, st[0]>>>(dinv);
    k_scan1<<<SCAN_BLK, 1024, 0, st[0]>>>(cnt, ptr, cur, bsum);
    k_scan2<<<1, 32, 0, st[0]>>>(bsum, boff, ptr);
    k_scan3<<<SCAN_BLK, 1024, 0, st[0]>>>(boff, ptr, cur);
    k_permute<<<(ET + TPB - 1) / TPB, TPB, 0, st[0]>>>(ei_all, w_all, dinv, cur, erow, enrm);

    // join branches, fork 4 timestep chains
    cudaStreamWaitEvent(st[0], evPrepG, 0);
    cudaEventRecord(evFork, st[0]);
    for (int i = 1; i < 4; i++) cudaStreamWaitEvent(st[i], evFork, 0);

    int aggBlocks = (Nn * 32 + TPB - 1) / TPB;
    dim3 ggrid((Nn + 127) / 128, Dd / 128);

    for (int t = 0; t < Tt; t++) {
        cudaStream_t s = st[t];
        __half* Hh = H[t];
        size_t xoff = (size_t)t * Nn * Dd;
        float* outT = out + xoff;

        for (int l = 0; l < 3; l++) {
            k_gemm_mma<<<ggrid, 256, GEMM_SMEM, s>>>(x + xoff,
                                                     wt + (size_t)l * Dd * Dd, Hh);
            bool last = (l == 2);
            k_aggregate<<<aggBlocks, TPB, 0, s>>>(ptr + (size_t)t * Nn, erow, enrm,
                                                  (const uint4*)Hh, dinv + (size_t)t * Nn,
                                                  (const float4*)bs[l],
                                                  last ? (float4*)outT : (float4*)nullptr,
                                                  last ? (uint4*)nullptr
                                                       : (uint4*)(x + xoff));
        }
    }

    // join all
    for (int i = 1; i < 4; i++) {
        cudaEventRecord(evJoin[i], st[i]);
        cudaStreamWaitEvent(st[0], evJoin[i], 0);
    }
}